// round 6
// baseline (speedup 1.0000x reference)
#include <cuda_runtime.h>

// EdgeClassification: logits[e] = emb[src]@Wsrc@Wcls + emb[dst]@Wdst@Wcls + (b_fuse@Wcls + b_cls)
// Restructure: fold weights (prep), project all nodes to 21-class tables (project),
// per-edge gather+add (edge). Tables padded to 32 floats = 128B = one full L2 line,
// gathered warp-cooperatively (8 lanes/edge) to minimize L1tex wavefronts.

#define D 128
#define NC 21
#define CP 32          // padded row: 32 floats = 128B = exactly one cache line
#define MAXN 50000
#define EPB 256        // edges per block in edge kernel
#define KCH 16         // k-chunk in prep

__device__ float g_Msrc[D * NC];
__device__ float g_Mdst[D * NC];
__device__ float g_bprime[NC];
__device__ float g_Psrc[MAXN * CP];
__device__ float g_Pdst[MAXN * CP];

// ---------------------------------------------------------------------------
// Kernel A: fold weights. grid=2 (one block per table), block=352.
// sWc holds Wcls; Wf staged in k-chunks of 16 with 129-pad (conflict-free).
// Block 0 also computes b' = b_cls + b_fuse @ Wcls.
// ---------------------------------------------------------------------------
__global__ void __launch_bounds__(352) prep_kernel(
    const float* __restrict__ Wsrc, const float* __restrict__ Wdst,
    const float* __restrict__ bfuse, const float* __restrict__ Wcls,
    const float* __restrict__ bcls)
{
    __shared__ float sWc[D * NC];       // 10752 B
    __shared__ float sWf[KCH * 129];    // 8256 B, padded rows
    const int tid = threadIdx.x;
    const int table = blockIdx.x;
    const float* __restrict__ Wf = table ? Wdst : Wsrc;
    float* __restrict__ M = table ? g_Mdst : g_Msrc;

    for (int i = tid; i < D * NC; i += 352) sWc[i] = Wcls[i];

    for (int kc = 0; kc < D; kc += KCH) {
        __syncthreads();
        // coalesced: consecutive i -> consecutive j within a k-row
        for (int i = tid; i < KCH * D; i += 352) {
            int k = i >> 7, j = i & 127;
            sWf[k * 129 + j] = Wf[(kc + k) * D + j];
        }
        __syncthreads();
        if (tid < KCH * NC) {
            int k = tid / NC, c = tid % NC;
            float acc = 0.f;
            #pragma unroll
            for (int j = 0; j < D; ++j)
                acc += sWf[k * 129 + j] * sWc[j * NC + c];
            M[(kc + k) * NC + c] = acc;
        }
    }
    if (table == 0 && tid < NC) {
        float acc = bcls[tid];
        for (int j = 0; j < D; ++j)
            acc += bfuse[j] * sWc[j * NC + tid];
        g_bprime[tid] = acc;
    }
}

// ---------------------------------------------------------------------------
// Kernel B: project all nodes through BOTH folded matrices in one pass.
// emb staged per 32-k chunk in smem (coalesced loads, 33-pad reads).
// 42 fp32 accumulators per thread (one node per thread).
// ---------------------------------------------------------------------------
__global__ void __launch_bounds__(128) project_kernel(
    const float* __restrict__ emb, int N)
{
    __shared__ float sMs[D * NC];     // 10752
    __shared__ float sMd[D * NC];     // 10752
    __shared__ float sb[NC];
    __shared__ float sE[128 * 33];    // 16896; total 38.5 KB

    const int tid = threadIdx.x;
    for (int i = tid; i < D * NC; i += 128) { sMs[i] = g_Msrc[i]; sMd[i] = g_Mdst[i]; }
    if (tid < NC) sb[tid] = g_bprime[tid];

    const int n0 = blockIdx.x * 128;
    float as[NC], ad[NC];
    __syncthreads();
    #pragma unroll
    for (int c = 0; c < NC; ++c) { as[c] = sb[c]; ad[c] = 0.f; }

    for (int kc = 0; kc < D; kc += 32) {
        if (kc) __syncthreads();
        // coalesced: 32 consecutive floats of one node row per 32 threads
        for (int i = tid; i < 128 * 32; i += 128) {
            int nl = i >> 5, k = i & 31;
            int n = n0 + nl;
            sE[nl * 33 + k] = (n < N) ? emb[(size_t)n * D + kc + k] : 0.f;
        }
        __syncthreads();
        #pragma unroll 4
        for (int k = 0; k < 32; ++k) {
            float v = sE[tid * 33 + k];
            const float* __restrict__ ms = &sMs[(kc + k) * NC];
            const float* __restrict__ md = &sMd[(kc + k) * NC];
            #pragma unroll
            for (int c = 0; c < NC; ++c) {
                as[c] = fmaf(v, ms[c], as[c]);
                ad[c] = fmaf(v, md[c], ad[c]);
            }
        }
    }

    const int n = n0 + tid;
    if (n >= N) return;
    float4* Ps = reinterpret_cast<float4*>(g_Psrc + (size_t)n * CP);
    float4* Pd = reinterpret_cast<float4*>(g_Pdst + (size_t)n * CP);
    #pragma unroll
    for (int q = 0; q < 5; ++q) {
        Ps[q] = make_float4(as[4*q], as[4*q+1], as[4*q+2], as[4*q+3]);
        Pd[q] = make_float4(ad[4*q], ad[4*q+1], ad[4*q+2], ad[4*q+3]);
    }
    Ps[5] = make_float4(as[20], 0.f, 0.f, 0.f);
    Pd[5] = make_float4(ad[20], 0.f, 0.f, 0.f);
}

// ---------------------------------------------------------------------------
// Kernel C: warp-cooperative gather. 8 lanes per edge, each lane loads one
// float4 of the 128B row -> gather instruction touches 4 lines (not 32).
// Indices staged in smem; results staged in smem for coalesced output.
// ---------------------------------------------------------------------------
__global__ void __launch_bounds__(EPB) edge_kernel(
    const int* __restrict__ ei32, float* __restrict__ out, int E)
{
    __shared__ float tile[EPB * NC];  // 21504
    __shared__ int   sidx[EPB * 2];   // 2048

    // dtype sniff: int64 => all high words zero (indices < 50000)
    const bool is64 = ((ei32[1] | ei32[3] | ei32[5] | ei32[7]) == 0);

    const int tid = threadIdx.x;
    const long long base = (long long)blockIdx.x * EPB;
    const int valid = (int)min((long long)EPB, (long long)E - base);

    if (is64) {
        const long long* ei = reinterpret_cast<const long long*>(ei32);
        for (int i = tid; i < valid; i += EPB) {
            sidx[i]       = (int)ei[base + i];
            sidx[EPB + i] = (int)ei[(long long)E + base + i];
        }
    } else {
        for (int i = tid; i < valid; i += EPB) {
            sidx[i]       = ei32[base + i];
            sidx[EPB + i] = ei32[(long long)E + base + i];
        }
    }
    __syncthreads();

    const int j  = tid & 7;   // float4 index within row
    const int eg = tid >> 3;  // edge slot: 32 concurrent edges per block-iter
    const int c0 = 4 * j;
    const float4* __restrict__ Ps4 = reinterpret_cast<const float4*>(g_Psrc);
    const float4* __restrict__ Pd4 = reinterpret_cast<const float4*>(g_Pdst);

    for (int el = eg; el < valid; el += 32) {
        const int s = sidx[el];
        const int d = sidx[EPB + el];
        float4 a = Ps4[(size_t)s * 8 + j];
        float4 b = Pd4[(size_t)d * 8 + j];
        // smem write addrs 21*el + 4j + k: conflict-free across the warp
        float* tp = &tile[el * NC + c0];
        if (c0 < 20) {
            tp[0] = a.x + b.x; tp[1] = a.y + b.y;
            tp[2] = a.z + b.z; tp[3] = a.w + b.w;
        } else if (c0 == 20) {
            tp[0] = a.x + b.x;
        }
    }
    __syncthreads();

    const int total = valid * NC;
    float* outp = out + base * NC;
    if ((total & 3) == 0) {
        float4* o4 = reinterpret_cast<float4*>(outp);
        const float4* t4 = reinterpret_cast<const float4*>(tile);
        const int nv = total >> 2;  // full block: 1344
        for (int i = tid; i < nv; i += EPB)
            o4[i] = t4[i];
    } else {
        for (int i = tid; i < total; i += EPB)
            outp[i] = tile[i];
    }
}

// ---------------------------------------------------------------------------
extern "C" void kernel_launch(void* const* d_in, const int* in_sizes, int n_in,
                              void* d_out, int out_size)
{
    const float* emb   = (const float*)d_in[0];
    const int*   ei    = (const int*)  d_in[1];   // width auto-detected in-kernel
    const float* Wsrc  = (const float*)d_in[2];
    const float* Wdst  = (const float*)d_in[3];
    const float* bfuse = (const float*)d_in[4];
    const float* Wcls  = (const float*)d_in[5];
    const float* bcls  = (const float*)d_in[6];
    float* out = (float*)d_out;

    int N = in_sizes[0] / D;
    if (N > MAXN) N = MAXN;
    int E = in_sizes[1] / 2;

    prep_kernel<<<2, 352>>>(Wsrc, Wdst, bfuse, Wcls, bcls);

    project_kernel<<<(N + 127) / 128, 128>>>(emb, N);

    edge_kernel<<<(E + EPB - 1) / EPB, EPB>>>(ei, out, E);
}

// round 9
// speedup vs baseline: 1.4378x; 1.4378x over previous
#include <cuda_runtime.h>

// EdgeClassification: logits[e] = emb[src]@Wsrc@Wcls + emb[dst]@Wdst@Wcls + (b_fuse@Wcls + b_cls)
// prep: fold weights, warp-per-output (full-chip parallel).
// project: all nodes -> 21-class tables, packed f32x2 FMA, smem-tiled.
// edge: warp-cooperative 96B gathers + coalesced smem-staged output.

#define D 128
#define NC 21
#define CP 32          // table row stride: 32 floats = 128B (row starts line-aligned;
                       // only first 96B = 3 sectors ever touched by gathers)
#define MP 24          // padded M row in project smem: 24 floats = 96B, 8B-aligned pairs
#define MAXN 50000
#define EPB 256

typedef unsigned long long ull;

__device__ float g_Msrc[D * NC];
__device__ float g_Mdst[D * NC];
__device__ float g_bprime[NC];
__device__ float g_Psrc[MAXN * CP];
__device__ float g_Pdst[MAXN * CP];

__device__ __forceinline__ void ffma2(ull& acc, ull a, ull b) {
    asm("fma.rn.f32x2 %0, %1, %2, %0;" : "+l"(acc) : "l"(a), "l"(b));
}
__device__ __forceinline__ ull pack2(float lo, float hi) {
    ull r; asm("mov.b64 %0, {%1, %2};" : "=l"(r) : "f"(lo), "f"(hi)); return r;
}
__device__ __forceinline__ void unpack2(ull v, float& lo, float& hi) {
    asm("mov.b64 {%0, %1}, %2;" : "=f"(lo), "=f"(hi) : "l"(v));
}

// ---------------------------------------------------------------------------
// Kernel A: fold weights. One warp per output element M_t[k][c].
// 5376 outputs -> blocks 0..671 (8 warps each). Blocks 672..674: bias b'.
// Lane j' = q*32+lane: Wf row read coalesced (128B); Wcls from smem,
// addresses (j*21+c) mod 32 distinct (21 coprime 32) -> conflict-free.
// ---------------------------------------------------------------------------
__global__ void __launch_bounds__(256) prep_kernel(
    const float* __restrict__ Wsrc, const float* __restrict__ Wdst,
    const float* __restrict__ bfuse, const float* __restrict__ Wcls,
    const float* __restrict__ bcls)
{
    __shared__ float sWc[D * NC];
    const int tid = threadIdx.x, lane = tid & 31, w = tid >> 5;
    for (int i = tid; i < D * NC; i += 256) sWc[i] = Wcls[i];
    __syncthreads();

    if (blockIdx.x < 672) {
        int gw = blockIdx.x * 8 + w;          // 0..5375
        int table = gw / (D * NC);
        int rem = gw - table * (D * NC);
        int k = rem / NC, c = rem - k * NC;
        const float* __restrict__ Wf = table ? Wdst : Wsrc;
        float p = 0.f;
        #pragma unroll
        for (int q = 0; q < 4; ++q) {
            int j = q * 32 + lane;
            p = fmaf(Wf[k * D + j], sWc[j * NC + c], p);
        }
        #pragma unroll
        for (int o = 16; o; o >>= 1) p += __shfl_xor_sync(0xffffffffu, p, o);
        if (lane == 0) (table ? g_Mdst : g_Msrc)[k * NC + c] = p;
    } else {
        int c = (blockIdx.x - 672) * 8 + w;
        if (c < NC) {
            float p = 0.f;
            #pragma unroll
            for (int q = 0; q < 4; ++q) {
                int j = q * 32 + lane;
                p = fmaf(bfuse[j], sWc[j * NC + c], p);
            }
            #pragma unroll
            for (int o = 16; o; o >>= 1) p += __shfl_xor_sync(0xffffffffu, p, o);
            if (lane == 0) g_bprime[c] = bcls[c] + p;
        }
    }
}

// ---------------------------------------------------------------------------
// Kernel B: project all nodes through both folded matrices, one pass.
// M rows padded to 24 floats in smem -> 8B-aligned f32x2 pairs, broadcast LDS.
// Packed fma.rn.f32x2 halves FMA-pipe ops (42 -> 22 per k per node).
// ---------------------------------------------------------------------------
__global__ void __launch_bounds__(128) project_kernel(
    const float* __restrict__ emb, int N)
{
    __shared__ float sMs[D * MP];     // 12 KB
    __shared__ float sMd[D * MP];     // 12 KB
    __shared__ float sb[NC];
    __shared__ float sE[128 * 33];    // 16.9 KB

    const int tid = threadIdx.x;
    for (int i = tid; i < D * NC; i += 128) {
        int k = i / NC, c = i - k * NC;
        sMs[k * MP + c] = g_Msrc[i];
        sMd[k * MP + c] = g_Mdst[i];
    }
    if (tid < NC) sb[tid] = g_bprime[tid];

    const int n0 = blockIdx.x * 128;
    ull as2[10], ad2[10];
    float as20, ad20;
    // init after first barrier below makes sb visible? sb written by this block's
    // own threads; read after the first __syncthreads() in the kc loop.
    bool inited = false;

    for (int kc = 0; kc < D; kc += 32) {
        __syncthreads();   // prior-chunk reads done; first iter: sM/sb fills visible
        if (!inited) {
            inited = true;
            #pragma unroll
            for (int q = 0; q < 10; ++q) {
                as2[q] = pack2(sb[2 * q], sb[2 * q + 1]);
                ad2[q] = 0ULL;
            }
            as20 = sb[20]; ad20 = 0.f;
        }
        // coalesced fill: warp w writes row nl=w+..., addr 33*nl+k conflict-free
        #pragma unroll
        for (int it = 0; it < 32; ++it) {
            int i = tid + it * 128;
            int nl = i >> 5, k = i & 31;
            int n = n0 + nl;
            sE[nl * 33 + k] = (n < N) ? emb[(size_t)n * D + kc + k] : 0.f;
        }
        __syncthreads();
        #pragma unroll 4
        for (int k = 0; k < 32; ++k) {
            float v = sE[tid * 33 + k];          // (tid + k) mod 32 distinct
            ull v2 = pack2(v, v);
            const float* __restrict__ mrs = &sMs[(kc + k) * MP];
            const float* __restrict__ mrd = &sMd[(kc + k) * MP];
            #pragma unroll
            for (int q = 0; q < 10; ++q) {
                ull ms = *reinterpret_cast<const ull*>(mrs + 2 * q);
                ull md = *reinterpret_cast<const ull*>(mrd + 2 * q);
                ffma2(as2[q], v2, ms);
                ffma2(ad2[q], v2, md);
            }
            as20 = fmaf(v, mrs[20], as20);
            ad20 = fmaf(v, mrd[20], ad20);
        }
    }

    const int n = n0 + tid;
    if (n >= N) return;
    float os[22], od[22];
    #pragma unroll
    for (int q = 0; q < 10; ++q) {
        unpack2(as2[q], os[2 * q], os[2 * q + 1]);
        unpack2(ad2[q], od[2 * q], od[2 * q + 1]);
    }
    os[20] = as20; od[20] = ad20;
    float4* Ps = reinterpret_cast<float4*>(g_Psrc + (size_t)n * CP);
    float4* Pd = reinterpret_cast<float4*>(g_Pdst + (size_t)n * CP);
    #pragma unroll
    for (int q = 0; q < 5; ++q) {
        Ps[q] = make_float4(os[4*q], os[4*q+1], os[4*q+2], os[4*q+3]);
        Pd[q] = make_float4(od[4*q], od[4*q+1], od[4*q+2], od[4*q+3]);
    }
    Ps[5] = make_float4(os[20], 0.f, 0.f, 0.f);
    Pd[5] = make_float4(od[20], 0.f, 0.f, 0.f);
}

// ---------------------------------------------------------------------------
// Kernel C: warp-cooperative gather. 8-lane groups per edge; only lanes
// j<=5 load (96B = 3 sectors per row; 4th sector is padding, never touched).
// Smem-staged results -> fully coalesced float4 output.
// ---------------------------------------------------------------------------
__global__ void __launch_bounds__(EPB) edge_kernel(
    const int* __restrict__ ei32, float* __restrict__ out, int E)
{
    __shared__ float tile[EPB * NC];  // 21504
    __shared__ int   sidx[EPB * 2];

    // dtype sniff: int64 => all high words zero (indices < 50000)
    const bool is64 = ((ei32[1] | ei32[3] | ei32[5] | ei32[7]) == 0);

    const int tid = threadIdx.x;
    const long long base = (long long)blockIdx.x * EPB;
    const int valid = (int)min((long long)EPB, (long long)E - base);

    if (is64) {
        const long long* ei = reinterpret_cast<const long long*>(ei32);
        for (int i = tid; i < valid; i += EPB) {
            sidx[i]       = (int)ei[base + i];
            sidx[EPB + i] = (int)ei[(long long)E + base + i];
        }
    } else {
        for (int i = tid; i < valid; i += EPB) {
            sidx[i]       = ei32[base + i];
            sidx[EPB + i] = ei32[(long long)E + base + i];
        }
    }
    __syncthreads();

    const int j  = tid & 7;
    const int eg = tid >> 3;
    const int c0 = 4 * j;
    const float4* __restrict__ Ps4 = reinterpret_cast<const float4*>(g_Psrc);
    const float4* __restrict__ Pd4 = reinterpret_cast<const float4*>(g_Pdst);

    if (c0 <= 20) {                       // lanes 6,7 idle: skip padding sector
        for (int el = eg; el < valid; el += 32) {
            const int s = sidx[el];
            const int d = sidx[EPB + el];
            float4 a = Ps4[(size_t)s * 8 + j];
            float4 b = Pd4[(size_t)d * 8 + j];
            float* tp = &tile[el * NC + c0];
            if (c0 < 20) {
                tp[0] = a.x + b.x; tp[1] = a.y + b.y;
                tp[2] = a.z + b.z; tp[3] = a.w + b.w;
            } else {
                tp[0] = a.x + b.x;
            }
        }
    }
    __syncthreads();

    const int total = valid * NC;
    float* outp = out + base * NC;
    if ((total & 3) == 0) {
        float4* o4 = reinterpret_cast<float4*>(outp);
        const float4* t4 = reinterpret_cast<const float4*>(tile);
        const int nv = total >> 2;
        for (int i = tid; i < nv; i += EPB)
            o4[i] = t4[i];
    } else {
        for (int i = tid; i < total; i += EPB)
            outp[i] = tile[i];
    }
}

// ---------------------------------------------------------------------------
extern "C" void kernel_launch(void* const* d_in, const int* in_sizes, int n_in,
                              void* d_out, int out_size)
{
    const float* emb   = (const float*)d_in[0];
    const int*   ei    = (const int*)  d_in[1];
    const float* Wsrc  = (const float*)d_in[2];
    const float* Wdst  = (const float*)d_in[3];
    const float* bfuse = (const float*)d_in[4];
    const float* Wcls  = (const float*)d_in[5];
    const float* bcls  = (const float*)d_in[6];
    float* out = (float*)d_out;

    int N = in_sizes[0] / D;
    if (N > MAXN) N = MAXN;
    int E = in_sizes[1] / 2;

    prep_kernel<<<675, 256>>>(Wsrc, Wdst, bfuse, Wcls, bcls);

    project_kernel<<<(N + 127) / 128, 128>>>(emb, N);

    edge_kernel<<<(E + EPB - 1) / EPB, EPB>>>(ei, out, E);
}

// round 11
// speedup vs baseline: 1.6916x; 1.1765x over previous
#include <cuda_runtime.h>
#include <cuda_fp16.h>

// EdgeClassification: logits[e] = emb[src]@Wsrc@Wcls + emb[dst]@Wdst@Wcls + (b_fuse@Wcls + b_cls)
// prep: fold weights (16 blocks, smem-staged, thread-per-output).
// project: all nodes -> 21-class tables (f32x2 FMA), stored as fp16 rows (64B).
// edge: warp-cooperative fp16 gathers (6x8B lanes/edge), MLP-batched, smem-staged output.

#define D 128
#define NC 21
#define MP 24          // padded M row in project smem
#define MAXN 50000
#define EPB 256

typedef unsigned long long ull;

__device__ float g_Msrc[D * NC];
__device__ float g_Mdst[D * NC];
__device__ float g_bprime[NC];
// fp16 projection tables: row = 32 halves = 64B (only first 24 halves = 48B ever read)
__device__ __align__(128) uint4 g_Psh[MAXN * 4];
__device__ __align__(128) uint4 g_Pdh[MAXN * 4];

__device__ __forceinline__ void ffma2(ull& acc, ull a, ull b) {
    asm("fma.rn.f32x2 %0, %1, %2, %0;" : "+l"(acc) : "l"(a), "l"(b));
}
__device__ __forceinline__ ull pack2(float lo, float hi) {
    ull r; asm("mov.b64 %0, {%1, %2};" : "=l"(r) : "f"(lo), "f"(hi)); return r;
}
__device__ __forceinline__ void unpack2(ull v, float& lo, float& hi) {
    asm("mov.b64 {%0, %1}, %2;" : "=f"(lo), "=f"(hi) : "l"(v));
}

// ---------------------------------------------------------------------------
// Kernel A: fold weights. 16 blocks = 2 tables x 8 k-chunks of 16 rows.
// Wf chunk (16x128, 129-pad) + Wcls staged in smem once; thread-per-output
// (336 outputs/block, threads 0..79 take a second). Block 0 threads 235..255
// also compute b' = b_cls + b_fuse @ Wcls.
// ---------------------------------------------------------------------------
__global__ void __launch_bounds__(256) prep_kernel(
    const float* __restrict__ Wsrc, const float* __restrict__ Wdst,
    const float* __restrict__ bfuse, const float* __restrict__ Wcls,
    const float* __restrict__ bcls)
{
    __shared__ float sWc[D * NC];       // 10752 B
    __shared__ float sWf[16 * 129];     // 8256 B
    const int tid = threadIdx.x;
    const int b = blockIdx.x;
    const int table = b >> 3;
    const int kc = (b & 7) * 16;
    const float* __restrict__ Wf = table ? Wdst : Wsrc;
    float* __restrict__ M = table ? g_Mdst : g_Msrc;

    for (int i = tid; i < D * NC; i += 256) sWc[i] = Wcls[i];
    for (int i = tid; i < 16 * D; i += 256) {
        int k = i >> 7, j = i & 127;
        sWf[k * 129 + j] = Wf[(size_t)(kc + k) * D + j];
    }
    __syncthreads();

    #pragma unroll
    for (int pass = 0; pass < 2; ++pass) {
        int o = tid + pass * 256;
        if (o < 16 * NC) {
            int k = o / NC, c = o - k * NC;
            float acc = 0.f;
            #pragma unroll
            for (int j = 0; j < D; ++j)
                acc = fmaf(sWf[k * 129 + j], sWc[j * NC + c], acc);
            M[(kc + k) * NC + c] = acc;
        }
    }
    if (b == 0 && tid >= 256 - NC) {
        int c = tid - (256 - NC);
        float acc = bcls[c];
        #pragma unroll 8
        for (int j = 0; j < D; ++j)
            acc = fmaf(bfuse[j], sWc[j * NC + c], acc);
        g_bprime[c] = acc;
    }
}

// ---------------------------------------------------------------------------
// Kernel B: project all nodes through both folded matrices, one pass.
// f32x2 packed FMAs; results converted to fp16 rows (24 halves used, 32 stride).
// ---------------------------------------------------------------------------
__global__ void __launch_bounds__(128) project_kernel(
    const float* __restrict__ emb, int N)
{
    __shared__ float sMs[D * MP];     // 12 KB
    __shared__ float sMd[D * MP];     // 12 KB
    __shared__ float sb[NC];
    __shared__ float sE[128 * 33];    // 16.9 KB

    const int tid = threadIdx.x;
    for (int i = tid; i < D * NC; i += 128) {
        int k = i / NC, c = i - k * NC;
        sMs[k * MP + c] = g_Msrc[i];
        sMd[k * MP + c] = g_Mdst[i];
    }
    if (tid < NC) sb[tid] = g_bprime[tid];

    const int n0 = blockIdx.x * 128;
    ull as2[10], ad2[10];
    float as20, ad20;
    bool inited = false;

    for (int kc = 0; kc < D; kc += 32) {
        __syncthreads();   // first iter: sM/sb visible; later: prior reads done
        if (!inited) {
            inited = true;
            #pragma unroll
            for (int q = 0; q < 10; ++q) {
                as2[q] = pack2(sb[2 * q], sb[2 * q + 1]);
                ad2[q] = 0ULL;
            }
            as20 = sb[20]; ad20 = 0.f;
        }
        #pragma unroll
        for (int it = 0; it < 32; ++it) {
            int i = tid + it * 128;
            int nl = i >> 5, k = i & 31;
            int n = n0 + nl;
            sE[nl * 33 + k] = (n < N) ? emb[(size_t)n * D + kc + k] : 0.f;
        }
        __syncthreads();
        #pragma unroll 4
        for (int k = 0; k < 32; ++k) {
            float v = sE[tid * 33 + k];
            ull v2 = pack2(v, v);
            const float* __restrict__ mrs = &sMs[(kc + k) * MP];
            const float* __restrict__ mrd = &sMd[(kc + k) * MP];
            #pragma unroll
            for (int q = 0; q < 10; ++q) {
                ull ms = *reinterpret_cast<const ull*>(mrs + 2 * q);
                ull md = *reinterpret_cast<const ull*>(mrd + 2 * q);
                ffma2(as2[q], v2, ms);
                ffma2(ad2[q], v2, md);
            }
            as20 = fmaf(v, mrs[20], as20);
            ad20 = fmaf(v, mrd[20], ad20);
        }
    }

    const int n = n0 + tid;
    if (n >= N) return;
    float os[22], od[22];
    #pragma unroll
    for (int q = 0; q < 10; ++q) {
        unpack2(as2[q], os[2 * q], os[2 * q + 1]);
        unpack2(ad2[q], od[2 * q], od[2 * q + 1]);
    }
    os[20] = as20; od[20] = ad20;
    os[21] = 0.f;  od[21] = 0.f;

    uint4 ws[3], wd[3];
    __half2* hs = reinterpret_cast<__half2*>(ws);
    __half2* hd = reinterpret_cast<__half2*>(wd);
    #pragma unroll
    for (int q = 0; q < 11; ++q) {
        hs[q] = __floats2half2_rn(os[2 * q], os[2 * q + 1]);
        hd[q] = __floats2half2_rn(od[2 * q], od[2 * q + 1]);
    }
    hs[11] = __floats2half2_rn(0.f, 0.f);
    hd[11] = __floats2half2_rn(0.f, 0.f);

    uint4* Ps = g_Psh + (size_t)n * 4;
    uint4* Pd = g_Pdh + (size_t)n * 4;
    #pragma unroll
    for (int q = 0; q < 3; ++q) { Ps[q] = ws[q]; Pd[q] = wd[q]; }
}

// ---------------------------------------------------------------------------
// Kernel C: warp-cooperative fp16 gather. 8-lane groups per edge, lanes j<=5
// each load 8B (4 halves = classes 4j..4j+3); 48B of the 64B row touched
// (2 sectors). Fast path batches 4 edges' loads (MLP=8/thread). Adds in fp32,
// smem-staged for fully coalesced float4 output.
// ---------------------------------------------------------------------------
__global__ void __launch_bounds__(EPB) edge_kernel(
    const int* __restrict__ ei32, float* __restrict__ out, int E)
{
    __shared__ float tile[EPB * NC];   // 21504
    __shared__ int   sidx[EPB * 2];    // interleaved (src,dst) pairs

    // dtype sniff: int64 => all high words zero (indices < 50000)
    const bool is64 = ((ei32[1] | ei32[3] | ei32[5] | ei32[7]) == 0);

    const int tid = threadIdx.x;
    const long long base = (long long)blockIdx.x * EPB;
    const int valid = (int)min((long long)EPB, (long long)E - base);

    if (is64) {
        const long long* ei = reinterpret_cast<const long long*>(ei32);
        for (int i = tid; i < valid; i += EPB) {
            sidx[2 * i]     = (int)ei[base + i];
            sidx[2 * i + 1] = (int)ei[(long long)E + base + i];
        }
    } else {
        for (int i = tid; i < valid; i += EPB) {
            sidx[2 * i]     = ei32[base + i];
            sidx[2 * i + 1] = ei32[(long long)E + base + i];
        }
    }
    __syncthreads();

    const int j  = tid & 7;
    const int eg = tid >> 3;
    const int c0 = 4 * j;
    const uint2* __restrict__ Ps2 = reinterpret_cast<const uint2*>(g_Psh);
    const uint2* __restrict__ Pd2 = reinterpret_cast<const uint2*>(g_Pdh);

    if (c0 <= 20) {
        if (valid == EPB) {
            // fast path: 8 iterations in two MLP-4 batches
            #pragma unroll
            for (int h = 0; h < 2; ++h) {
                int2 p[4]; uint2 A[4], B[4];
                #pragma unroll
                for (int it = 0; it < 4; ++it) {
                    int el = eg + 32 * (4 * h + it);
                    p[it] = *reinterpret_cast<const int2*>(&sidx[2 * el]);
                }
                #pragma unroll
                for (int it = 0; it < 4; ++it) {
                    A[it] = Ps2[(size_t)p[it].x * 8 + j];
                    B[it] = Pd2[(size_t)p[it].y * 8 + j];
                }
                #pragma unroll
                for (int it = 0; it < 4; ++it) {
                    int el = eg + 32 * (4 * h + it);
                    const __half2* ah = reinterpret_cast<const __half2*>(&A[it]);
                    const __half2* bh = reinterpret_cast<const __half2*>(&B[it]);
                    float2 fa0 = __half22float2(ah[0]), fb0 = __half22float2(bh[0]);
                    float* tp = &tile[el * NC + c0];
                    if (c0 < 20) {
                        float2 fa1 = __half22float2(ah[1]), fb1 = __half22float2(bh[1]);
                        tp[0] = fa0.x + fb0.x; tp[1] = fa0.y + fb0.y;
                        tp[2] = fa1.x + fb1.x; tp[3] = fa1.y + fb1.y;
                    } else {
                        tp[0] = fa0.x + fb0.x;
                    }
                }
            }
        } else {
            for (int el = eg; el < valid; el += 32) {
                int s = sidx[2 * el], d = sidx[2 * el + 1];
                uint2 A = Ps2[(size_t)s * 8 + j];
                uint2 B = Pd2[(size_t)d * 8 + j];
                const __half2* ah = reinterpret_cast<const __half2*>(&A);
                const __half2* bh = reinterpret_cast<const __half2*>(&B);
                float2 fa0 = __half22float2(ah[0]), fb0 = __half22float2(bh[0]);
                float* tp = &tile[el * NC + c0];
                if (c0 < 20) {
                    float2 fa1 = __half22float2(ah[1]), fb1 = __half22float2(bh[1]);
                    tp[0] = fa0.x + fb0.x; tp[1] = fa0.y + fb0.y;
                    tp[2] = fa1.x + fb1.x; tp[3] = fa1.y + fb1.y;
                } else {
                    tp[0] = fa0.x + fb0.x;
                }
            }
        }
    }
    __syncthreads();

    const int total = valid * NC;
    float* outp = out + base * NC;
    if ((total & 3) == 0) {
        float4* o4 = reinterpret_cast<float4*>(outp);
        const float4* t4 = reinterpret_cast<const float4*>(tile);
        const int nv = total >> 2;
        for (int i = tid; i < nv; i += EPB)
            o4[i] = t4[i];
    } else {
        for (int i = tid; i < total; i += EPB)
            outp[i] = tile[i];
    }
}

// ---------------------------------------------------------------------------
extern "C" void kernel_launch(void* const* d_in, const int* in_sizes, int n_in,
                              void* d_out, int out_size)
{
    const float* emb   = (const float*)d_in[0];
    const int*   ei    = (const int*)  d_in[1];
    const float* Wsrc  = (const float*)d_in[2];
    const float* Wdst  = (const float*)d_in[3];
    const float* bfuse = (const float*)d_in[4];
    const float* Wcls  = (const float*)d_in[5];
    const float* bcls  = (const float*)d_in[6];
    float* out = (float*)d_out;

    int N = in_sizes[0] / D;
    if (N > MAXN) N = MAXN;
    int E = in_sizes[1] / 2;

    prep_kernel<<<16, 256>>>(Wsrc, Wdst, bfuse, Wcls, bcls);

    project_kernel<<<(N + 127) / 128, 128>>>(emb, N);

    edge_kernel<<<(E + EPB - 1) / EPB, EPB>>>(ei, out, E);
}

// round 12
// speedup vs baseline: 1.7734x; 1.0483x over previous
#include <cuda_runtime.h>
#include <cuda_fp16.h>

// EdgeClassification: logits[e] = emb[src]@Wsrc@Wcls + emb[dst]@Wdst@Wcls + (b_fuse@Wcls + b_cls)
// prep: fold weights, thread-per-output, no smem/barriers (broadcast+coalesced loads).
// project: all nodes -> 21-class tables (f32x2 FMA), stored as fp16 rows (64B).
// edge: warp-cooperative fp16 gathers (6x8B lanes/edge), MLP-8 batched, smem-staged output.

#define D 128
#define NC 21
#define MP 24          // padded M row in project smem
#define MAXN 50000
#define EPB 256

typedef unsigned long long ull;

__device__ float g_Msrc[D * NC];
__device__ float g_Mdst[D * NC];
__device__ float g_bprime[NC];
// fp16 projection tables: row = 32 halves = 64B (only first 24 halves = 48B ever read)
__device__ __align__(128) uint4 g_Psh[MAXN * 4];
__device__ __align__(128) uint4 g_Pdh[MAXN * 4];

__device__ __forceinline__ void ffma2(ull& acc, ull a, ull b) {
    asm("fma.rn.f32x2 %0, %1, %2, %0;" : "+l"(acc) : "l"(a), "l"(b));
}
__device__ __forceinline__ ull pack2(float lo, float hi) {
    ull r; asm("mov.b64 %0, {%1, %2};" : "=l"(r) : "f"(lo), "f"(hi)); return r;
}
__device__ __forceinline__ void unpack2(ull v, float& lo, float& hi) {
    asm("mov.b64 {%0, %1}, %2;" : "=f"(lo), "=f"(hi) : "l"(v));
}

// ---------------------------------------------------------------------------
// Kernel A: fold weights. Thread-per-output, 22 blocks x 256 = 5632 threads
// for 5376 M-elements + 21 bias elements. No smem, no barriers.
// Warp access pattern: Wf[k*D+j] broadcast (21 consecutive threads share k),
// Wcls[j*NC+c] coalesced (consecutive c). 4 accumulators break the FMA chain.
// ---------------------------------------------------------------------------
__global__ void __launch_bounds__(256) prep_kernel(
    const float* __restrict__ Wsrc, const float* __restrict__ Wdst,
    const float* __restrict__ bfuse, const float* __restrict__ Wcls,
    const float* __restrict__ bcls)
{
    const int o = blockIdx.x * 256 + threadIdx.x;
    if (o < 2 * D * NC) {
        const int table = o / (D * NC);
        const int rem = o - table * (D * NC);
        const int k = rem / NC, c = rem - k * NC;
        const float* __restrict__ Wf = (table ? Wdst : Wsrc) + (size_t)k * D;
        const float* __restrict__ Wc = Wcls + c;
        float a0 = 0.f, a1 = 0.f, a2 = 0.f, a3 = 0.f;
        #pragma unroll
        for (int j = 0; j < D; j += 4) {
            a0 = fmaf(Wf[j],     Wc[(j)     * NC], a0);
            a1 = fmaf(Wf[j + 1], Wc[(j + 1) * NC], a1);
            a2 = fmaf(Wf[j + 2], Wc[(j + 2) * NC], a2);
            a3 = fmaf(Wf[j + 3], Wc[(j + 3) * NC], a3);
        }
        (table ? g_Mdst : g_Msrc)[k * NC + c] = (a0 + a1) + (a2 + a3);
    } else if (o < 2 * D * NC + NC) {
        const int c = o - 2 * D * NC;
        float a = bcls[c];
        #pragma unroll 8
        for (int j = 0; j < D; ++j)
            a = fmaf(bfuse[j], Wcls[j * NC + c], a);
        g_bprime[c] = a;
    }
}

// ---------------------------------------------------------------------------
// Kernel B: project all nodes through both folded matrices, one pass.
// f32x2 packed FMAs; results converted to fp16 rows (24 halves used, 32 stride).
// ---------------------------------------------------------------------------
__global__ void __launch_bounds__(128) project_kernel(
    const float* __restrict__ emb, int N)
{
    __shared__ float sMs[D * MP];     // 12 KB
    __shared__ float sMd[D * MP];     // 12 KB
    __shared__ float sb[NC];
    __shared__ float sE[128 * 33];    // 16.9 KB

    const int tid = threadIdx.x;
    for (int i = tid; i < D * NC; i += 128) {
        int k = i / NC, c = i - k * NC;
        sMs[k * MP + c] = g_Msrc[i];
        sMd[k * MP + c] = g_Mdst[i];
    }
    if (tid < NC) sb[tid] = g_bprime[tid];

    const int n0 = blockIdx.x * 128;
    ull as2[10], ad2[10];
    float as20, ad20;
    bool inited = false;

    for (int kc = 0; kc < D; kc += 32) {
        __syncthreads();   // first iter: sM/sb visible; later: prior reads done
        if (!inited) {
            inited = true;
            #pragma unroll
            for (int q = 0; q < 10; ++q) {
                as2[q] = pack2(sb[2 * q], sb[2 * q + 1]);
                ad2[q] = 0ULL;
            }
            as20 = sb[20]; ad20 = 0.f;
        }
        #pragma unroll
        for (int it = 0; it < 32; ++it) {
            int i = tid + it * 128;
            int nl = i >> 5, k = i & 31;
            int n = n0 + nl;
            sE[nl * 33 + k] = (n < N) ? emb[(size_t)n * D + kc + k] : 0.f;
        }
        __syncthreads();
        #pragma unroll 4
        for (int k = 0; k < 32; ++k) {
            float v = sE[tid * 33 + k];
            ull v2 = pack2(v, v);
            const float* __restrict__ mrs = &sMs[(kc + k) * MP];
            const float* __restrict__ mrd = &sMd[(kc + k) * MP];
            #pragma unroll
            for (int q = 0; q < 10; ++q) {
                ull ms = *reinterpret_cast<const ull*>(mrs + 2 * q);
                ull md = *reinterpret_cast<const ull*>(mrd + 2 * q);
                ffma2(as2[q], v2, ms);
                ffma2(ad2[q], v2, md);
            }
            as20 = fmaf(v, mrs[20], as20);
            ad20 = fmaf(v, mrd[20], ad20);
        }
    }

    const int n = n0 + tid;
    if (n >= N) return;
    float os[22], od[22];
    #pragma unroll
    for (int q = 0; q < 10; ++q) {
        unpack2(as2[q], os[2 * q], os[2 * q + 1]);
        unpack2(ad2[q], od[2 * q], od[2 * q + 1]);
    }
    os[20] = as20; od[20] = ad20;
    os[21] = 0.f;  od[21] = 0.f;

    uint4 ws[3], wd[3];
    __half2* hs = reinterpret_cast<__half2*>(ws);
    __half2* hd = reinterpret_cast<__half2*>(wd);
    #pragma unroll
    for (int q = 0; q < 11; ++q) {
        hs[q] = __floats2half2_rn(os[2 * q], os[2 * q + 1]);
        hd[q] = __floats2half2_rn(od[2 * q], od[2 * q + 1]);
    }
    hs[11] = __floats2half2_rn(0.f, 0.f);
    hd[11] = __floats2half2_rn(0.f, 0.f);

    uint4* Ps = g_Psh + (size_t)n * 4;
    uint4* Pd = g_Pdh + (size_t)n * 4;
    #pragma unroll
    for (int q = 0; q < 3; ++q) { Ps[q] = ws[q]; Pd[q] = wd[q]; }
}

// ---------------------------------------------------------------------------
// Kernel C: warp-cooperative fp16 gather. 8-lane groups per edge, lanes j<=5
// each load 8B (4 halves = classes 4j..4j+3); 48B of the 64B row touched
// (2 sectors). Fast path issues all 8 iterations' gathers up front
// (16 outstanding LDG.64/thread). Adds in fp32, smem-staged coalesced output.
// ---------------------------------------------------------------------------
__global__ void __launch_bounds__(EPB) edge_kernel(
    const int* __restrict__ ei32, float* __restrict__ out, int E)
{
    __shared__ float tile[EPB * NC];   // 21504
    __shared__ int   sidx[EPB * 2];    // interleaved (src,dst) pairs

    // dtype sniff: int64 => all high words zero (indices < 50000)
    const bool is64 = ((ei32[1] | ei32[3] | ei32[5] | ei32[7]) == 0);

    const int tid = threadIdx.x;
    const long long base = (long long)blockIdx.x * EPB;
    const int valid = (int)min((long long)EPB, (long long)E - base);

    if (is64) {
        const long long* ei = reinterpret_cast<const long long*>(ei32);
        for (int i = tid; i < valid; i += EPB) {
            sidx[2 * i]     = (int)ei[base + i];
            sidx[2 * i + 1] = (int)ei[(long long)E + base + i];
        }
    } else {
        for (int i = tid; i < valid; i += EPB) {
            sidx[2 * i]     = ei32[base + i];
            sidx[2 * i + 1] = ei32[(long long)E + base + i];
        }
    }
    __syncthreads();

    const int j  = tid & 7;
    const int eg = tid >> 3;
    const int c0 = 4 * j;
    const uint2* __restrict__ Ps2 = reinterpret_cast<const uint2*>(g_Psh);
    const uint2* __restrict__ Pd2 = reinterpret_cast<const uint2*>(g_Pdh);

    if (c0 <= 20) {
        if (valid == EPB) {
            // fast path: all 8 iterations' gathers issued before any use (MLP=16)
            int2 p[8]; uint2 A[8], B[8];
            #pragma unroll
            for (int it = 0; it < 8; ++it) {
                int el = eg + 32 * it;
                p[it] = *reinterpret_cast<const int2*>(&sidx[2 * el]);
            }
            #pragma unroll
            for (int it = 0; it < 8; ++it) {
                A[it] = Ps2[(size_t)p[it].x * 8 + j];
                B[it] = Pd2[(size_t)p[it].y * 8 + j];
            }
            #pragma unroll
            for (int it = 0; it < 8; ++it) {
                int el = eg + 32 * it;
                const __half2* ah = reinterpret_cast<const __half2*>(&A[it]);
                const __half2* bh = reinterpret_cast<const __half2*>(&B[it]);
                float2 fa0 = __half22float2(ah[0]), fb0 = __half22float2(bh[0]);
                float* tp = &tile[el * NC + c0];
                if (c0 < 20) {
                    float2 fa1 = __half22float2(ah[1]), fb1 = __half22float2(bh[1]);
                    tp[0] = fa0.x + fb0.x; tp[1] = fa0.y + fb0.y;
                    tp[2] = fa1.x + fb1.x; tp[3] = fa1.y + fb1.y;
                } else {
                    tp[0] = fa0.x + fb0.x;
                }
            }
        } else {
            for (int el = eg; el < valid; el += 32) {
                int s = sidx[2 * el], d = sidx[2 * el + 1];
                uint2 A = Ps2[(size_t)s * 8 + j];
                uint2 B = Pd2[(size_t)d * 8 + j];
                const __half2* ah = reinterpret_cast<const __half2*>(&A);
                const __half2* bh = reinterpret_cast<const __half2*>(&B);
                float2 fa0 = __half22float2(ah[0]), fb0 = __half22float2(bh[0]);
                float* tp = &tile[el * NC + c0];
                if (c0 < 20) {
                    float2 fa1 = __half22float2(ah[1]), fb1 = __half22float2(bh[1]);
                    tp[0] = fa0.x + fb0.x; tp[1] = fa0.y + fb0.y;
                    tp[2] = fa1.x + fb1.x; tp[3] = fa1.y + fb1.y;
                } else {
                    tp[0] = fa0.x + fb0.x;
                }
            }
        }
    }
    __syncthreads();

    float* outp = out + base * NC;
    if (valid == EPB) {
        // 1344 float4 = 5*EPB + 64: compile-time unrolled
        float4* o4 = reinterpret_cast<float4*>(outp);
        const float4* t4 = reinterpret_cast<const float4*>(tile);
        #pragma unroll
        for (int it = 0; it < 5; ++it)
            o4[tid + it * EPB] = t4[tid + it * EPB];
        if (tid < 64)
            o4[tid + 5 * EPB] = t4[tid + 5 * EPB];
    } else {
        const int total = valid * NC;
        for (int i = tid; i < total; i += EPB)
            outp[i] = tile[i];
    }
}

// ---------------------------------------------------------------------------
extern "C" void kernel_launch(void* const* d_in, const int* in_sizes, int n_in,
                              void* d_out, int out_size)
{
    const float* emb   = (const float*)d_in[0];
    const int*   ei    = (const int*)  d_in[1];
    const float* Wsrc  = (const float*)d_in[2];
    const float* Wdst  = (const float*)d_in[3];
    const float* bfuse = (const float*)d_in[4];
    const float* Wcls  = (const float*)d_in[5];
    const float* bcls  = (const float*)d_in[6];
    float* out = (float*)d_out;

    int N = in_sizes[0] / D;
    if (N > MAXN) N = MAXN;
    int E = in_sizes[1] / 2;

    prep_kernel<<<(2 * D * NC + NC + 255) / 256, 256>>>(Wsrc, Wdst, bfuse, Wcls, bcls);

    project_kernel<<<(N + 127) / 128, 128>>>(emb, N);

    edge_kernel<<<(E + EPB - 1) / EPB, EPB>>>(ei, out, E);
}

// round 13
// speedup vs baseline: 1.8628x; 1.0504x over previous
#include <cuda_runtime.h>
#include <cuda_fp16.h>

// EdgeClassification: logits[e] = emb[src]@Wsrc@Wcls + emb[dst]@Wdst@Wcls + (b_fuse@Wcls + b_cls)
// prep: fold weights, 4-lane-split dots + shfl reduce (latency-parallel).
// project: all nodes -> 21-class tables (f32x2 FMA), stored as fp16 rows (64B).
// edge: warp-cooperative fp16 gathers (6x8B lanes/edge), MLP-16 batched, smem-staged output.

#define D 128
#define NC 21
#define MP 24          // padded M row in project smem
#define MAXN 50000
#define EPB 256

typedef unsigned long long ull;

__device__ float g_Msrc[D * NC];
__device__ float g_Mdst[D * NC];
__device__ float g_bprime[NC];
// fp16 projection tables: row = 32 halves = 64B (only first 24 halves = 48B ever read)
__device__ __align__(128) uint4 g_Psh[MAXN * 4];
__device__ __align__(128) uint4 g_Pdh[MAXN * 4];

__device__ __forceinline__ void ffma2(ull& acc, ull a, ull b) {
    asm("fma.rn.f32x2 %0, %1, %2, %0;" : "+l"(acc) : "l"(a), "l"(b));
}
__device__ __forceinline__ ull pack2(float lo, float hi) {
    ull r; asm("mov.b64 %0, {%1, %2};" : "=l"(r) : "f"(lo), "f"(hi)); return r;
}
__device__ __forceinline__ void unpack2(ull v, float& lo, float& hi) {
    asm("mov.b64 {%0, %1}, %2;" : "=f"(lo), "=f"(hi) : "l"(v));
}

// ---------------------------------------------------------------------------
// Kernel A: fold weights. Each output's 128-dot split across 4 consecutive
// lanes (q = t&3, 32 j's each), reduced with 2 shfl_xor. 4x the threads and
// 1/4 the serial loads per thread vs thread-per-output -> latency-parallel.
// Outputs 0..5375: M tables. Outputs 5376..5396: bias b'.
// ---------------------------------------------------------------------------
__global__ void __launch_bounds__(256) prep_kernel(
    const float* __restrict__ Wsrc, const float* __restrict__ Wdst,
    const float* __restrict__ bfuse, const float* __restrict__ Wcls,
    const float* __restrict__ bcls)
{
    const int t = blockIdx.x * 256 + threadIdx.x;
    const int o = t >> 2;            // output id
    const int q = t & 3;             // j-quarter
    if (o >= 2 * D * NC + NC) return;

    float a0 = 0.f, a1 = 0.f;
    if (o < 2 * D * NC) {
        const int table = o / (D * NC);
        const int rem = o - table * (D * NC);
        const int k = rem / NC, c = rem - k * NC;
        const float* __restrict__ Wf = (table ? Wdst : Wsrc) + (size_t)k * D + q * 32;
        const float* __restrict__ Wc = Wcls + q * 32 * NC + c;
        #pragma unroll
        for (int jj = 0; jj < 32; jj += 2) {
            a0 = fmaf(Wf[jj],     Wc[jj * NC],       a0);
            a1 = fmaf(Wf[jj + 1], Wc[(jj + 1) * NC], a1);
        }
        a0 += a1;
        a0 += __shfl_xor_sync(0xffffffffu, a0, 1);
        a0 += __shfl_xor_sync(0xffffffffu, a0, 2);
        if (q == 0)
            (table ? g_Mdst : g_Msrc)[k * NC + c] = a0;
    } else {
        const int c = o - 2 * D * NC;
        const float* __restrict__ Wc = Wcls + q * 32 * NC + c;
        const float* __restrict__ bf = bfuse + q * 32;
        #pragma unroll
        for (int jj = 0; jj < 32; jj += 2) {
            a0 = fmaf(bf[jj],     Wc[jj * NC],       a0);
            a1 = fmaf(bf[jj + 1], Wc[(jj + 1) * NC], a1);
        }
        a0 += a1;
        a0 += __shfl_xor_sync(0xffffffffu, a0, 1);
        a0 += __shfl_xor_sync(0xffffffffu, a0, 2);
        if (q == 0)
            g_bprime[c] = bcls[c] + a0;
    }
}

// ---------------------------------------------------------------------------
// Kernel B: project all nodes through both folded matrices, one pass.
// f32x2 packed FMAs; results converted to fp16 rows (24 halves used, 32 stride).
// ---------------------------------------------------------------------------
__global__ void __launch_bounds__(128) project_kernel(
    const float* __restrict__ emb, int N)
{
    __shared__ float sMs[D * MP];     // 12 KB
    __shared__ float sMd[D * MP];     // 12 KB
    __shared__ float sb[NC];
    __shared__ float sE[128 * 33];    // 16.9 KB

    const int tid = threadIdx.x;
    for (int i = tid; i < D * NC; i += 128) {
        int k = i / NC, c = i - k * NC;
        sMs[k * MP + c] = g_Msrc[i];
        sMd[k * MP + c] = g_Mdst[i];
    }
    if (tid < NC) sb[tid] = g_bprime[tid];

    const int n0 = blockIdx.x * 128;
    ull as2[10], ad2[10];
    float as20, ad20;
    bool inited = false;

    for (int kc = 0; kc < D; kc += 32) {
        __syncthreads();   // first iter: sM/sb visible; later: prior reads done
        if (!inited) {
            inited = true;
            #pragma unroll
            for (int q = 0; q < 10; ++q) {
                as2[q] = pack2(sb[2 * q], sb[2 * q + 1]);
                ad2[q] = 0ULL;
            }
            as20 = sb[20]; ad20 = 0.f;
        }
        #pragma unroll
        for (int it = 0; it < 32; ++it) {
            int i = tid + it * 128;
            int nl = i >> 5, k = i & 31;
            int n = n0 + nl;
            sE[nl * 33 + k] = (n < N) ? emb[(size_t)n * D + kc + k] : 0.f;
        }
        __syncthreads();
        #pragma unroll 4
        for (int k = 0; k < 32; ++k) {
            float v = sE[tid * 33 + k];
            ull v2 = pack2(v, v);
            const float* __restrict__ mrs = &sMs[(kc + k) * MP];
            const float* __restrict__ mrd = &sMd[(kc + k) * MP];
            #pragma unroll
            for (int q = 0; q < 10; ++q) {
                ull ms = *reinterpret_cast<const ull*>(mrs + 2 * q);
                ull md = *reinterpret_cast<const ull*>(mrd + 2 * q);
                ffma2(as2[q], v2, ms);
                ffma2(ad2[q], v2, md);
            }
            as20 = fmaf(v, mrs[20], as20);
            ad20 = fmaf(v, mrd[20], ad20);
        }
    }

    const int n = n0 + tid;
    if (n >= N) return;
    float os[22], od[22];
    #pragma unroll
    for (int q = 0; q < 10; ++q) {
        unpack2(as2[q], os[2 * q], os[2 * q + 1]);
        unpack2(ad2[q], od[2 * q], od[2 * q + 1]);
    }
    os[20] = as20; od[20] = ad20;
    os[21] = 0.f;  od[21] = 0.f;

    uint4 ws[3], wd[3];
    __half2* hs = reinterpret_cast<__half2*>(ws);
    __half2* hd = reinterpret_cast<__half2*>(wd);
    #pragma unroll
    for (int q = 0; q < 11; ++q) {
        hs[q] = __floats2half2_rn(os[2 * q], os[2 * q + 1]);
        hd[q] = __floats2half2_rn(od[2 * q], od[2 * q + 1]);
    }
    hs[11] = __floats2half2_rn(0.f, 0.f);
    hd[11] = __floats2half2_rn(0.f, 0.f);

    uint4* Ps = g_Psh + (size_t)n * 4;
    uint4* Pd = g_Pdh + (size_t)n * 4;
    #pragma unroll
    for (int q = 0; q < 3; ++q) { Ps[q] = ws[q]; Pd[q] = wd[q]; }
}

// ---------------------------------------------------------------------------
// Kernel C: warp-cooperative fp16 gather. 8-lane groups per edge, lanes j<=5
// each load 8B (4 halves = classes 4j..4j+3); 48B of the 64B row touched
// (2 sectors). Fast path issues all 8 iterations' gathers up front
// (16 outstanding LDG.64/thread). Adds in fp32, smem-staged coalesced output.
// ---------------------------------------------------------------------------
__global__ void __launch_bounds__(EPB) edge_kernel(
    const int* __restrict__ ei32, float* __restrict__ out, int E)
{
    __shared__ float tile[EPB * NC];   // 21504
    __shared__ int   sidx[EPB * 2];    // interleaved (src,dst) pairs

    // dtype sniff: int64 => all high words zero (indices < 50000)
    const bool is64 = ((ei32[1] | ei32[3] | ei32[5] | ei32[7]) == 0);

    const int tid = threadIdx.x;
    const long long base = (long long)blockIdx.x * EPB;
    const int valid = (int)min((long long)EPB, (long long)E - base);

    if (is64) {
        const long long* ei = reinterpret_cast<const long long*>(ei32);
        for (int i = tid; i < valid; i += EPB) {
            sidx[2 * i]     = (int)ei[base + i];
            sidx[2 * i + 1] = (int)ei[(long long)E + base + i];
        }
    } else {
        for (int i = tid; i < valid; i += EPB) {
            sidx[2 * i]     = ei32[base + i];
            sidx[2 * i + 1] = ei32[(long long)E + base + i];
        }
    }
    __syncthreads();

    const int j  = tid & 7;
    const int eg = tid >> 3;
    const int c0 = 4 * j;
    const uint2* __restrict__ Ps2 = reinterpret_cast<const uint2*>(g_Psh);
    const uint2* __restrict__ Pd2 = reinterpret_cast<const uint2*>(g_Pdh);

    if (c0 <= 20) {
        if (valid == EPB) {
            // fast path: all 8 iterations' gathers issued before any use (MLP=16)
            int2 p[8]; uint2 A[8], B[8];
            #pragma unroll
            for (int it = 0; it < 8; ++it) {
                int el = eg + 32 * it;
                p[it] = *reinterpret_cast<const int2*>(&sidx[2 * el]);
            }
            #pragma unroll
            for (int it = 0; it < 8; ++it) {
                A[it] = Ps2[(size_t)p[it].x * 8 + j];
                B[it] = Pd2[(size_t)p[it].y * 8 + j];
            }
            #pragma unroll
            for (int it = 0; it < 8; ++it) {
                int el = eg + 32 * it;
                const __half2* ah = reinterpret_cast<const __half2*>(&A[it]);
                const __half2* bh = reinterpret_cast<const __half2*>(&B[it]);
                float2 fa0 = __half22float2(ah[0]), fb0 = __half22float2(bh[0]);
                float* tp = &tile[el * NC + c0];
                if (c0 < 20) {
                    float2 fa1 = __half22float2(ah[1]), fb1 = __half22float2(bh[1]);
                    tp[0] = fa0.x + fb0.x; tp[1] = fa0.y + fb0.y;
                    tp[2] = fa1.x + fb1.x; tp[3] = fa1.y + fb1.y;
                } else {
                    tp[0] = fa0.x + fb0.x;
                }
            }
        } else {
            for (int el = eg; el < valid; el += 32) {
                int s = sidx[2 * el], d = sidx[2 * el + 1];
                uint2 A = Ps2[(size_t)s * 8 + j];
                uint2 B = Pd2[(size_t)d * 8 + j];
                const __half2* ah = reinterpret_cast<const __half2*>(&A);
                const __half2* bh = reinterpret_cast<const __half2*>(&B);
                float2 fa0 = __half22float2(ah[0]), fb0 = __half22float2(bh[0]);
                float* tp = &tile[el * NC + c0];
                if (c0 < 20) {
                    float2 fa1 = __half22float2(ah[1]), fb1 = __half22float2(bh[1]);
                    tp[0] = fa0.x + fb0.x; tp[1] = fa0.y + fb0.y;
                    tp[2] = fa1.x + fb1.x; tp[3] = fa1.y + fb1.y;
                } else {
                    tp[0] = fa0.x + fb0.x;
                }
            }
        }
    }
    __syncthreads();

    float* outp = out + base * NC;
    if (valid == EPB) {
        // 1344 float4 = 5*EPB + 64: compile-time unrolled
        float4* o4 = reinterpret_cast<float4*>(outp);
        const float4* t4 = reinterpret_cast<const float4*>(tile);
        #pragma unroll
        for (int it = 0; it < 5; ++it)
            o4[tid + it * EPB] = t4[tid + it * EPB];
        if (tid < 64)
            o4[tid + 5 * EPB] = t4[tid + 5 * EPB];
    } else {
        const int total = valid * NC;
        for (int i = tid; i < total; i += EPB)
            outp[i] = tile[i];
    }
}

// ---------------------------------------------------------------------------
extern "C" void kernel_launch(void* const* d_in, const int* in_sizes, int n_in,
                              void* d_out, int out_size)
{
    const float* emb   = (const float*)d_in[0];
    const int*   ei    = (const int*)  d_in[1];
    const float* Wsrc  = (const float*)d_in[2];
    const float* Wdst  = (const float*)d_in[3];
    const float* bfuse = (const float*)d_in[4];
    const float* Wcls  = (const float*)d_in[5];
    const float* bcls  = (const float*)d_in[6];
    float* out = (float*)d_out;

    int N = in_sizes[0] / D;
    if (N > MAXN) N = MAXN;
    int E = in_sizes[1] / 2;

    const int prep_threads = 4 * (2 * D * NC + NC);
    prep_kernel<<<(prep_threads + 255) / 256, 256>>>(Wsrc, Wdst, bfuse, Wcls, bcls);

    project_kernel<<<(N + 127) / 128, 128>>>(emb, N);

    edge_kernel<<<(E + EPB - 1) / EPB, EPB>>>(ei, out, E);
}